// round 13
// baseline (speedup 1.0000x reference)
#include <cuda_runtime.h>
#include <math.h>

#define TDIM 600
#define BATCH 32
#define NBUF (BATCH*128*TDIM)
#define PLANE (16*TDIM)
#define PSLOT (BATCH*PLANE)
#define CCOLS 620
#define CHAIN_SMEM ((2*16*CCOLS + 768)*4)
#define GEMM_SMEM ((2*32*132 + 2*32*68 + 3*128)*4)

typedef unsigned long long u64;

__device__ __forceinline__ u64 dup2(float a){
    u64 r; asm("mov.b64 %0, {%1, %1};" : "=l"(r) : "f"(a)); return r;
}
__device__ __forceinline__ void upk2(u64 v, float& a, float& b){
    asm("mov.b64 {%0, %1}, %2;" : "=f"(a), "=f"(b) : "l"(v));
}
__device__ __forceinline__ u64 f2fma(u64 a, u64 b, u64 c){
    u64 d; asm("fma.rn.f32x2 %0, %1, %2, %3;" : "=l"(d) : "l"(a), "l"(b), "l"(c)); return d;
}
__device__ __forceinline__ void cpa16(unsigned dst, const void* src){
    asm volatile("cp.async.ca.shared.global [%0], [%1], 16;" :: "r"(dst), "l"(src));
}
__device__ __forceinline__ void cpa16z(unsigned dst, const void* src, int sz){
    asm volatile("cp.async.ca.shared.global [%0], [%1], 16, %2;" :: "r"(dst), "l"(src), "r"(sz));
}
__device__ __forceinline__ void cpcommit(){ asm volatile("cp.async.commit_group;"); }
template<int N> __device__ __forceinline__ void cpwait(){
    asm volatile("cp.async.wait_group %0;" :: "n"(N));
}

__device__ __align__(1024) float g_in[NBUF];
__device__ __align__(1024) float g_o1[NBUF];
__device__ __align__(1024) float g_o2[NBUF];
__device__ __align__(1024) float g_o3[NBUF];
__device__ __align__(1024) float g_pl[35*PSLOT];
__device__ __align__(1024) float g_wt[14*16384];
__device__ float g_spart[BATCH*128*10];
__device__ float g_pool[BATCH*1024];

// transpose 14 128x128 weight matrices into g_wt[k][o]
__global__ __launch_bounds__(256) void k_tr(
    const float* __restrict__ W1, const float* __restrict__ W3,
    float* __restrict__ Wt)
{
    __shared__ float t[32][33];
    const int m = blockIdx.y;
    const int r0 = (blockIdx.x >> 2) * 32, c0 = (blockIdx.x & 3) * 32;
    const float* src = (m < 7) ? (W1 + m*16384) : (W3 + (m-7)*16384);
    float* dst = Wt + m*16384;
    const int x = threadIdx.x, y = threadIdx.y;
    #pragma unroll
    for (int k = 0; k < 4; ++k)
        t[y + 8*k][x] = src[(r0 + y + 8*k)*128 + c0 + x];
    __syncthreads();
    #pragma unroll
    for (int k = 0; k < 4; ++k)
        dst[(c0 + y + 8*k)*128 + r0 + x] = t[x][y + 8*k];
}

// out[b,o,t] = bn(relu(sum_k Wt[k,o]*in[b,k,t] + bias[o]))
// optional: spart[b][o][chunk] = per-t-block partial sums for SE squeeze
__global__ __launch_bounds__(256) void k_gemm(
    const float* __restrict__ Wt, const float* __restrict__ bias,
    const float* __restrict__ bn,
    const float* __restrict__ in, long long inStr,
    float* __restrict__ out, float* __restrict__ spart)
{
    extern __shared__ float sm[];
    float* WsF = sm;                 // [2][32][132]
    float* BsF = sm + 2*32*132;      // [2][32][68]
    float* sA  = sm + 2*32*132 + 2*32*68;
    float* sBb = sA + 128;
    float* sBi = sA + 256;

    const int b = blockIdx.y, t0 = blockIdx.x*64, tid = threadIdx.x;

    if (tid < 128) {
        float g=bn[tid], be=bn[128+tid], mm=bn[256+tid], vv=bn[384+tid];
        float a = g*rsqrtf(vv+1e-5f);
        sA[tid]=a; sBb[tid]=be-mm*a; sBi[tid]=bias[tid];
    }
    const float* pA = in + (long long)b*inStr;

    unsigned smU = (unsigned)__cvta_generic_to_shared(sm);
    const unsigned wsU = smU;
    const unsigned bsU = smU + 2*32*132*4;

    u64 acc2[4][4];
    #pragma unroll
    for (int rr=0;rr<4;++rr)
        #pragma unroll
        for (int q=0;q<4;++q) acc2[rr][q]=0ull;

    const int tx = tid&15, ty = tid>>4;
    const int cBase = tx*4, rBase = ty*8;

    auto loadTile = [&](int k0, int buf){
        #pragma unroll
        for (int it=0;it<4;++it){
            int idx = it*256 + tid;
            int kk = idx >> 5, c4 = (idx & 31) << 2;
            cpa16(wsU + (unsigned)((buf*4224 + kk*132 + c4)*4),
                  Wt + (k0+kk)*128 + c4);
        }
        #pragma unroll
        for (int it=0;it<2;++it){
            int idx = it*256 + tid;
            int kk = idx >> 4, c4 = (idx & 15) << 2;
            int t = t0 + c4;
            int sz = (t + 3 < TDIM) ? 16 : 0;
            const float* src = sz ? (pA + (long long)(k0+kk)*TDIM + t) : pA;
            cpa16z(bsU + (unsigned)((buf*2176 + kk*68 + c4)*4), src, sz);
        }
    };

    loadTile(0, 0);
    cpcommit();

    #pragma unroll
    for (int p=0;p<4;++p){
        if (p<3){ loadTile((p+1)*32, (p+1)&1); cpcommit(); cpwait<1>(); }
        else cpwait<0>();
        __syncthreads();
        const float* Wb = WsF + (p&1)*4224;
        const float* Bb = BsF + (p&1)*2176;
        #pragma unroll
        for (int kk=0;kk<32;++kk){
            ulonglong2 w01 = *reinterpret_cast<const ulonglong2*>(Wb + kk*132 + rBase);
            ulonglong2 w23 = *reinterpret_cast<const ulonglong2*>(Wb + kk*132 + rBase + 4);
            float4 bv = *reinterpret_cast<const float4*>(Bb + kk*68 + cBase);
            u64 bq[4] = {dup2(bv.x), dup2(bv.y), dup2(bv.z), dup2(bv.w)};
            u64 aq[4] = {w01.x, w01.y, w23.x, w23.y};
            #pragma unroll
            for (int rr=0;rr<4;++rr)
                #pragma unroll
                for (int q=0;q<4;++q)
                    acc2[rr][q] = f2fma(aq[rr], bq[q], acc2[rr][q]);
        }
        if (p<3) __syncthreads();
    }

    const bool valid = (t0+cBase+3 < TDIM);
    float rs[8];
    #pragma unroll
    for (int k=0;k<8;++k) rs[k]=0.f;

    if (valid){
        float* po = out + ((long long)b*128 + rBase)*TDIM + t0 + cBase;
        #pragma unroll
        for (int rr=0;rr<4;++rr){
            float lo[4], hi[4];
            #pragma unroll
            for (int q=0;q<4;++q) upk2(acc2[rr][q], lo[q], hi[q]);
            int o0 = rBase + 2*rr, o1 = o0 + 1;
            float a0=sA[o0], c0=sBb[o0], bi0=sBi[o0];
            float a1=sA[o1], c1=sBb[o1], bi1=sBi[o1];
            float4 v0, v1;
            v0.x=fmaxf(lo[0]+bi0,0.f)*a0+c0; v0.y=fmaxf(lo[1]+bi0,0.f)*a0+c0;
            v0.z=fmaxf(lo[2]+bi0,0.f)*a0+c0; v0.w=fmaxf(lo[3]+bi0,0.f)*a0+c0;
            v1.x=fmaxf(hi[0]+bi1,0.f)*a1+c1; v1.y=fmaxf(hi[1]+bi1,0.f)*a1+c1;
            v1.z=fmaxf(hi[2]+bi1,0.f)*a1+c1; v1.w=fmaxf(hi[3]+bi1,0.f)*a1+c1;
            *reinterpret_cast<float4*>(po + 2*rr*TDIM)     = v0;
            *reinterpret_cast<float4*>(po + (2*rr+1)*TDIM) = v1;
            rs[2*rr]   = (v0.x+v0.y)+(v0.z+v0.w);
            rs[2*rr+1] = (v1.x+v1.y)+(v1.z+v1.w);
        }
    }
    if (spart){
        #pragma unroll
        for (int d=8; d; d>>=1)
            #pragma unroll
            for (int k=0;k<8;++k)
                rs[k] += __shfl_down_sync(0xffffffffu, rs[k], d);
        if (tx == 0){
            #pragma unroll
            for (int k=0;k<8;++k)
                spart[((long long)b*128 + rBase + k)*10 + blockIdx.x] = rs[k];
        }
    }
}

// Fused inner-conv chain: one block per (batch b, plane s).
// 12 outputs per thread-pass: taps span exactly the loaded 18 floats.
__global__ __launch_bounds__(256) void k_chain(
    const float* __restrict__ o1,
    const float* __restrict__ cw,
    const float* __restrict__ cb,
    const float* __restrict__ ibn,
    float* __restrict__ pl)
{
    extern __shared__ float csm[];
    float* bufA = csm;
    float* bufB = csm + 16*CCOLS;
    float* wsm  = csm + 32*CCOLS;

    const int b = blockIdx.x, s = blockIdx.y;
    const int tid = threadIdx.x;
    const int o = tid & 15, g = tid >> 4;
    const int j0 = (s == 0) ? 0 : s - 1;
    const int srcRow = (s == 0) ? 112 : (s - 1) * 16;
    const float* src = o1 + ((long long)b*128 + srcRow)*TDIM;

    for (int idx = tid; idx < 16*20*2; idx += 256) {
        int bsel = idx >= 16*20;
        int rem  = idx - bsel*16*20;
        int r = rem / 20, hc = rem - r*20;
        int c = (hc < 4) ? hc : 600 + hc;
        (bsel ? bufB : bufA)[r*CCOLS + c] = 0.f;
    }
    for (int idx = tid; idx < 16*TDIM; idx += 256) {
        int r = idx / TDIM, t = idx - r*TDIM;
        bufA[r*CCOLS + 4 + t] = src[idx];
    }

    float* cur = bufA;
    float* nxt = bufB;

    for (int j = j0; j < 7; ++j) {
        __syncthreads();
        const float* cwj = cw + j*768;
        for (int idx = tid; idx < 768; idx += 256) wsm[idx] = cwj[idx];
        __syncthreads();

        float rw[48];
        #pragma unroll
        for (int q = 0; q < 12; ++q)
            *reinterpret_cast<float4*>(&rw[q*4]) =
                *reinterpret_cast<const float4*>(&wsm[o*48 + q*4]);
        const float cb0 = __ldg(cb + j*16 + o);
        const float* ib = ibn + j*64;
        float gg=__ldg(ib+o), be=__ldg(ib+16+o), mm=__ldg(ib+32+o), vv=__ldg(ib+48+o);
        float bnA = gg*rsqrtf(vv+1e-5f), bnB = be - mm*bnA;

        // 12 outputs per pass: tb = 12*(g + 16p), p = 0..3, slot < 50
        #pragma unroll
        for (int p = 0; p < 4; ++p) {
            int slot = g + 16*p;
            if (slot < 50) {
                int tb = slot*12;
                u64 acc2[6];
                u64 cbd = dup2(cb0);
                #pragma unroll
                for (int xx=0;xx<6;++xx) acc2[xx]=cbd;
                #pragma unroll
                for (int i=0;i<16;++i){
                    const float* row = cur + i*CCOLS + tb;
                    ulonglong2 va = *reinterpret_cast<const ulonglong2*>(row);
                    ulonglong2 vb = *reinterpret_cast<const ulonglong2*>(row+4);
                    ulonglong2 vc = *reinterpret_cast<const ulonglong2*>(row+8);
                    ulonglong2 vd = *reinterpret_cast<const ulonglong2*>(row+12);
                    u64 ve = *reinterpret_cast<const u64*>(row+16);
                    u64 v2[9] = {va.x,va.y,vb.x,vb.y,vc.x,vc.y,vd.x,vd.y,ve};
                    #pragma unroll
                    for (int k=0;k<3;++k){
                        u64 w2 = dup2(rw[i*3+k]);
                        #pragma unroll
                        for (int xx=0;xx<6;++xx)
                            acc2[xx] = f2fma(w2, v2[xx+1+k], acc2[xx]);
                    }
                }
                float ov[12];
                #pragma unroll
                for (int xx=0;xx<6;++xx){
                    float lo, hi; upk2(acc2[xx], lo, hi);
                    ov[2*xx]   = fmaxf(lo,0.f)*bnA + bnB;
                    ov[2*xx+1] = fmaxf(hi,0.f)*bnA + bnB;
                }
                float* orow = nxt + o*CCOLS + 4 + tb;
                *reinterpret_cast<float4*>(orow)   = make_float4(ov[0],ov[1],ov[2],ov[3]);
                *reinterpret_cast<float4*>(orow+4) = make_float4(ov[4],ov[5],ov[6],ov[7]);
                *reinterpret_cast<float4*>(orow+8) = make_float4(ov[8],ov[9],ov[10],ov[11]);
            }
        }
        __syncthreads();
        const int slotIdx = j*(j+3)/2 + s;
        float* dst = pl + (long long)slotIdx*PSLOT + (long long)b*PLANE;
        for (int idx = tid; idx < 16*TDIM; idx += 256) {
            int r = idx / TDIM, t = idx - r*TDIM;
            dst[idx] = nxt[r*CCOLS + 4 + t];
        }
        float* tmp = cur; cur = nxt; nxt = tmp;
    }
}

// grid (32 b, 8 j, 6 seg); threads <200 each handle 2 consecutive float4.
struct WSP { const float* w[7]; };
__global__ __launch_bounds__(256) void k_wsum(
    const float* __restrict__ pl, WSP wsp,
    const float* __restrict__ o1, float* __restrict__ o2)
{
    const int b = blockIdx.x, j = blockIdx.y, seg = blockIdx.z;
    const int tid = threadIdx.x;
    const int v0 = seg*400;
    if (tid >= 200) return;
    const int v = v0 + 2*tid;

    if (j == 7){
        const float4* s4 = reinterpret_cast<const float4*>(o1 + ((long long)b*128 + 112)*TDIM);
        float4* d4 = reinterpret_cast<float4*>(o2 + ((long long)b*128 + 112)*TDIM);
        float4 p0 = __ldg(s4 + v);
        float4 p1 = __ldg(s4 + v + 1);
        d4[v] = p0; d4[v+1] = p1;
        return;
    }
    const int off = j*(j+3)/2;
    const int S = j+2;
    float w[8];
    #pragma unroll
    for (int s=0;s<8;++s) w[s] = (s<S) ? __ldg(wsp.w[j]+s) : 0.f;
    const float4* base = reinterpret_cast<const float4*>(pl + (long long)off*PSLOT + (long long)b*PLANE);
    float4* dst = reinterpret_cast<float4*>(o2 + ((long long)b*128 + j*16)*TDIM);
    const int slotV = PSLOT/4;

    float4 a0 = make_float4(0.f,0.f,0.f,0.f);
    float4 a1 = make_float4(0.f,0.f,0.f,0.f);
    float4 b0 = make_float4(0.f,0.f,0.f,0.f);
    float4 b1 = make_float4(0.f,0.f,0.f,0.f);
    #pragma unroll
    for (int s=0;s<8;s+=2){
        if (s < S){
            float4 p = __ldg(base + (long long)s*slotV + v);
            float4 q = __ldg(base + (long long)s*slotV + v + 1);
            a0.x=fmaf(w[s],p.x,a0.x); a0.y=fmaf(w[s],p.y,a0.y);
            a0.z=fmaf(w[s],p.z,a0.z); a0.w=fmaf(w[s],p.w,a0.w);
            b0.x=fmaf(w[s],q.x,b0.x); b0.y=fmaf(w[s],q.y,b0.y);
            b0.z=fmaf(w[s],q.z,b0.z); b0.w=fmaf(w[s],q.w,b0.w);
        }
        if (s+1 < S){
            float4 p = __ldg(base + (long long)(s+1)*slotV + v);
            float4 q = __ldg(base + (long long)(s+1)*slotV + v + 1);
            a1.x=fmaf(w[s+1],p.x,a1.x); a1.y=fmaf(w[s+1],p.y,a1.y);
            a1.z=fmaf(w[s+1],p.z,a1.z); a1.w=fmaf(w[s+1],p.w,a1.w);
            b1.x=fmaf(w[s+1],q.x,b1.x); b1.y=fmaf(w[s+1],q.y,b1.y);
            b1.z=fmaf(w[s+1],q.z,b1.z); b1.w=fmaf(w[s+1],q.w,b1.w);
        }
    }
    dst[v]   = make_float4(a0.x+a1.x, a0.y+a1.y, a0.z+a1.z, a0.w+a1.w);
    dst[v+1] = make_float4(b0.x+b1.x, b0.y+b1.y, b0.z+b1.z, b0.w+b1.w);
}

// apply with SE fused: each block recomputes the SE MLP from spart (cheap,
// L1-resident), then v = o3*se_c + resid; sp = bn_o(relu(v)); nIn = sp+xNext;
// pooled[b,gcBase+c] = mean_t relu(bn_f(sp))
__global__ __launch_bounds__(128) void k_apply(
    const float* __restrict__ o3, const float* __restrict__ spart,
    const float* __restrict__ s1w, const float* __restrict__ s1b,
    const float* __restrict__ s2w, const float* __restrict__ s2b,
    const float* __restrict__ resid, long long rStr,
    const float* __restrict__ xNext, float* nIn,
    const float* __restrict__ obn, const float* __restrict__ fbn, int gcBase,
    float* __restrict__ pooled)
{
    __shared__ float m[128], s1[16], scSh;
    const int c=blockIdx.x, b=blockIdx.y, tid=threadIdx.x;
    const int gc=gcBase+c;

    // SE squeeze + FC1 + FC2(row c) — redundant per block, tiny
    {
        const float* p = spart + ((long long)b*128 + tid)*10;
        float s = 0.f;
        #pragma unroll
        for (int q=0;q<10;++q) s += p[q];
        m[tid] = s*(1.f/600.f);
    }
    __syncthreads();
    if (tid<16){
        float s=s1b[tid];
        for (int k=0;k<128;++k) s=fmaf(s1w[tid*128+k],m[k],s);
        s1[tid]=fmaxf(s,0.f);
    }
    __syncthreads();
    if (tid==0){
        float s=s2b[c];
        #pragma unroll
        for (int oo=0;oo<16;++oo) s=fmaf(s2w[c*16+oo],s1[oo],s);
        scSh = 1.f/(1.f+expf(-s));
    }
    __syncthreads();
    const float sc = scSh;

    float oA=obn[c]*rsqrtf(obn[384+c]+1e-5f);
    float oB=obn[128+c]-obn[256+c]*oA;
    float fA=fbn[gc]*rsqrtf(fbn[3072+gc]+1e-5f);
    float fB=fbn[1024+gc]-fbn[2048+gc]*fA;
    const float4* p3 = reinterpret_cast<const float4*>(o3 + ((long long)b*128+c)*TDIM);
    const float4* pr = reinterpret_cast<const float4*>(resid + (long long)b*rStr + (long long)c*TDIM);
    const float4* pn = xNext ? reinterpret_cast<const float4*>(xNext + (long long)b*1024*TDIM + (long long)c*TDIM) : nullptr;
    float4* po = reinterpret_cast<float4*>(nIn + ((long long)b*128+c)*TDIM);
    float s=0.f;
    for (int v=tid; v<150; v+=128){
        float4 a = __ldg(p3 + v);
        float4 r = __ldg(pr + v);
        float4 spv;
        spv.x = fmaxf(a.x*sc + r.x, 0.f)*oA + oB;
        spv.y = fmaxf(a.y*sc + r.y, 0.f)*oA + oB;
        spv.z = fmaxf(a.z*sc + r.z, 0.f)*oA + oB;
        spv.w = fmaxf(a.w*sc + r.w, 0.f)*oA + oB;
        if (pn){
            float4 n = __ldg(pn + v);
            po[v] = make_float4(spv.x+n.x, spv.y+n.y, spv.z+n.z, spv.w+n.w);
        }
        s += fmaxf(spv.x*fA+fB,0.f) + fmaxf(spv.y*fA+fB,0.f)
           + fmaxf(spv.z*fA+fB,0.f) + fmaxf(spv.w*fA+fB,0.f);
    }
    __shared__ float red[128];
    red[tid]=s; __syncthreads();
    for (int o=64;o;o>>=1){ if(tid<o) red[tid]+=red[tid+o]; __syncthreads(); }
    if (!tid) pooled[b*1024+gc]=red[0]*(1.f/600.f);
}

__global__ __launch_bounds__(128) void k_ptail(
    const float* __restrict__ x, const float* __restrict__ fbn,
    float* __restrict__ pooled)
{
    const int c=blockIdx.x, b=blockIdx.y, tid=threadIdx.x;
    const int gc=896+c;
    float fA=fbn[gc]*rsqrtf(fbn[3072+gc]+1e-5f);
    float fB=fbn[1024+gc]-fbn[2048+gc]*fA;
    const float4* px = reinterpret_cast<const float4*>(x + ((long long)b*1024+gc)*TDIM);
    float s=0.f;
    for (int v=tid; v<150; v+=128){
        float4 p = __ldg(px + v);
        s += fmaxf(p.x*fA+fB,0.f) + fmaxf(p.y*fA+fB,0.f)
           + fmaxf(p.z*fA+fB,0.f) + fmaxf(p.w*fA+fB,0.f);
    }
    __shared__ float red[128];
    red[tid]=s; __syncthreads();
    for (int o=64;o;o>>=1){ if(tid<o) red[tid]+=red[tid+o]; __syncthreads(); }
    if (!tid) pooled[b*1024+gc]=red[0]*(1.f/600.f);
}

__global__ __launch_bounds__(256) void k_fc(
    const float* __restrict__ pooled, const float* __restrict__ fcw,
    const float* __restrict__ fcb, float* __restrict__ out)
{
    const int b=blockIdx.x, tid=threadIdx.x;
    float s0=0.f, s1=0.f;
    for (int c=tid;c<1024;c+=256){
        float p=pooled[b*1024+c];
        s0=fmaf(p,fcw[c],s0);
        s1=fmaf(p,fcw[1024+c],s1);
    }
    __shared__ float r0[256], r1[256];
    r0[tid]=s0; r1[tid]=s1; __syncthreads();
    for (int o=128;o;o>>=1){ if(tid<o){r0[tid]+=r0[tid+o]; r1[tid]+=r1[tid+o];} __syncthreads(); }
    if (!tid){ out[b*2]=r0[0]+fcb[0]; out[b*2+1]=r1[0]+fcb[1]; }
}

extern "C" void kernel_launch(void* const* d_in, const int* in_sizes, int n_in,
                              void* d_out, int out_size)
{
    const float* P[25] = {nullptr};
    int n896=0, n3584=0, n114688=0, n14336=0;
    for (int i=0;i<n_in;++i){
        int s=in_sizes[i]; const float* p=(const float*)d_in[i];
        switch(s){
            case 19660800: P[0]=p; break;
            case 114688: P[n114688++?14:1]=p; break;
            case 896: P[n896==0?2:(n896==1?15:20)]=p; n896++; break;
            case 3584: P[n3584==0?3:(n3584==1?16:21)]=p; n3584++; break;
            case 37632: P[4]=p; break;
            case 784: P[5]=p; break;
            case 3136: P[6]=p; break;
            case 14: P[7]=p; break;  case 21: P[8]=p; break;
            case 28: P[9]=p; break;  case 35: P[10]=p; break;
            case 42: P[11]=p; break; case 49: P[12]=p; break;
            case 56: P[13]=p; break;
            case 14336: P[n14336++?19:17]=p; break;
            case 112: P[18]=p; break;
            case 4096: P[22]=p; break;
            case 2048: P[23]=p; break;
            case 2: P[24]=p; break;
            default: break;
        }
    }
    float *gin,*o1,*o2,*o3,*pl,*wt,*spart,*pool;
    cudaGetSymbolAddress((void**)&gin, g_in);
    cudaGetSymbolAddress((void**)&o1, g_o1);
    cudaGetSymbolAddress((void**)&o2, g_o2);
    cudaGetSymbolAddress((void**)&o3, g_o3);
    cudaGetSymbolAddress((void**)&pl, g_pl);
    cudaGetSymbolAddress((void**)&wt, g_wt);
    cudaGetSymbolAddress((void**)&spart, g_spart);
    cudaGetSymbolAddress((void**)&pool, g_pool);
    float* out = (float*)d_out;

    cudaFuncSetAttribute(k_chain, cudaFuncAttributeMaxDynamicSharedMemorySize, CHAIN_SMEM);
    cudaFuncSetAttribute(k_gemm,  cudaFuncAttributeMaxDynamicSharedMemorySize, GEMM_SMEM);

    k_tr<<<dim3(16,14),dim3(32,8)>>>(P[1], P[14], wt);

    dim3 gG(10,32);
    for (int i=0;i<7;++i){
        const float* xi = P[0] + (long long)i*128*TDIM;
        k_gemm<<<gG,256,GEMM_SMEM>>>(wt + i*16384, P[2]+i*128, P[3]+i*512,
                                     i? gin : xi, i? 128LL*TDIM : 1024LL*TDIM, o1, nullptr);
        k_chain<<<dim3(32,8),256,CHAIN_SMEM>>>(o1,
            P[4]+i*7*768, P[5]+i*7*16, P[6]+i*7*64, pl);
        WSP wsp;
        for (int j=0;j<7;++j) wsp.w[j] = P[7+j] + i*(j+2);
        k_wsum<<<dim3(32,8,6),256>>>(pl, wsp, o1, o2);
        k_gemm<<<gG,256,GEMM_SMEM>>>(wt + (7+i)*16384, P[15]+i*128, P[16]+i*512,
                                     o2, 128LL*TDIM, o3, spart);
        const float* xNext = (i<6) ? (P[0] + (long long)(i+1)*128*TDIM) : nullptr;
        k_apply<<<dim3(128,32),128>>>(o3, spart,
                                      P[17]+i*2048, P[18]+i*16, P[19]+i*2048, P[20]+i*128,
                                      i? gin : xi, i? 128LL*TDIM : 1024LL*TDIM,
                                      xNext, gin,
                                      P[21]+i*512, P[22], i*128, pool);
    }
    k_ptail<<<dim3(128,32),128>>>(P[0], P[22], pool);
    k_fc<<<32,256>>>(pool, P[23], P[24], out);
}

// round 14
// speedup vs baseline: 1.5579x; 1.5579x over previous
#include <cuda_runtime.h>
#include <math.h>

#define TDIM 600
#define BATCH 32
#define NBUF (BATCH*128*TDIM)
#define PLANE (16*TDIM)
#define PSLOT (BATCH*PLANE)
#define CCOLS 620
#define CHAIN_SMEM ((2*16*CCOLS + 768)*4)
#define GEMM_SMEM ((2*32*132 + 2*32*68 + 3*128)*4)

typedef unsigned long long u64;

__device__ __forceinline__ u64 dup2(float a){
    u64 r; asm("mov.b64 %0, {%1, %1};" : "=l"(r) : "f"(a)); return r;
}
__device__ __forceinline__ void upk2(u64 v, float& a, float& b){
    asm("mov.b64 {%0, %1}, %2;" : "=f"(a), "=f"(b) : "l"(v));
}
__device__ __forceinline__ u64 f2fma(u64 a, u64 b, u64 c){
    u64 d; asm("fma.rn.f32x2 %0, %1, %2, %3;" : "=l"(d) : "l"(a), "l"(b), "l"(c)); return d;
}
__device__ __forceinline__ void cpa16(unsigned dst, const void* src){
    asm volatile("cp.async.ca.shared.global [%0], [%1], 16;" :: "r"(dst), "l"(src));
}
__device__ __forceinline__ void cpa16z(unsigned dst, const void* src, int sz){
    asm volatile("cp.async.ca.shared.global [%0], [%1], 16, %2;" :: "r"(dst), "l"(src), "r"(sz));
}
__device__ __forceinline__ void cpcommit(){ asm volatile("cp.async.commit_group;"); }
template<int N> __device__ __forceinline__ void cpwait(){
    asm volatile("cp.async.wait_group %0;" :: "n"(N));
}

__device__ __align__(1024) float g_in[NBUF];
__device__ __align__(1024) float g_o1[NBUF];
__device__ __align__(1024) float g_o2[NBUF];
__device__ __align__(1024) float g_o3[NBUF];
__device__ __align__(1024) float g_pl[35*PSLOT];
__device__ __align__(1024) float g_wt[14*16384];
__device__ float g_spart[BATCH*128*10];
__device__ float g_pool[BATCH*1024];

// transpose 14 128x128 weight matrices into g_wt[k][o]
__global__ __launch_bounds__(256) void k_tr(
    const float* __restrict__ W1, const float* __restrict__ W3,
    float* __restrict__ Wt)
{
    __shared__ float t[32][33];
    const int m = blockIdx.y;
    const int r0 = (blockIdx.x >> 2) * 32, c0 = (blockIdx.x & 3) * 32;
    const float* src = (m < 7) ? (W1 + m*16384) : (W3 + (m-7)*16384);
    float* dst = Wt + m*16384;
    const int x = threadIdx.x, y = threadIdx.y;
    #pragma unroll
    for (int k = 0; k < 4; ++k)
        t[y + 8*k][x] = src[(r0 + y + 8*k)*128 + c0 + x];
    __syncthreads();
    #pragma unroll
    for (int k = 0; k < 4; ++k)
        dst[(c0 + y + 8*k)*128 + r0 + x] = t[x][y + 8*k];
}

// out[b,o,t] = bn(relu(sum_k Wt[k,o]*in[b,k,t] + bias[o]))
// optional: spart[b][o][chunk] = per-t-block partial sums for SE squeeze
__global__ __launch_bounds__(256) void k_gemm(
    const float* __restrict__ Wt, const float* __restrict__ bias,
    const float* __restrict__ bn,
    const float* __restrict__ in, long long inStr,
    float* __restrict__ out, float* __restrict__ spart)
{
    extern __shared__ float sm[];
    float* WsF = sm;                 // [2][32][132]
    float* BsF = sm + 2*32*132;      // [2][32][68]
    float* sA  = sm + 2*32*132 + 2*32*68;
    float* sBb = sA + 128;
    float* sBi = sA + 256;

    const int b = blockIdx.y, t0 = blockIdx.x*64, tid = threadIdx.x;

    if (tid < 128) {
        float g=bn[tid], be=bn[128+tid], mm=bn[256+tid], vv=bn[384+tid];
        float a = g*rsqrtf(vv+1e-5f);
        sA[tid]=a; sBb[tid]=be-mm*a; sBi[tid]=bias[tid];
    }
    const float* pA = in + (long long)b*inStr;

    unsigned smU = (unsigned)__cvta_generic_to_shared(sm);
    const unsigned wsU = smU;
    const unsigned bsU = smU + 2*32*132*4;

    u64 acc2[4][4];
    #pragma unroll
    for (int rr=0;rr<4;++rr)
        #pragma unroll
        for (int q=0;q<4;++q) acc2[rr][q]=0ull;

    const int tx = tid&15, ty = tid>>4;
    const int cBase = tx*4, rBase = ty*8;

    auto loadTile = [&](int k0, int buf){
        #pragma unroll
        for (int it=0;it<4;++it){
            int idx = it*256 + tid;
            int kk = idx >> 5, c4 = (idx & 31) << 2;
            cpa16(wsU + (unsigned)((buf*4224 + kk*132 + c4)*4),
                  Wt + (k0+kk)*128 + c4);
        }
        #pragma unroll
        for (int it=0;it<2;++it){
            int idx = it*256 + tid;
            int kk = idx >> 4, c4 = (idx & 15) << 2;
            int t = t0 + c4;
            int sz = (t + 3 < TDIM) ? 16 : 0;
            const float* src = sz ? (pA + (long long)(k0+kk)*TDIM + t) : pA;
            cpa16z(bsU + (unsigned)((buf*2176 + kk*68 + c4)*4), src, sz);
        }
    };

    loadTile(0, 0);
    cpcommit();

    #pragma unroll
    for (int p=0;p<4;++p){
        if (p<3){ loadTile((p+1)*32, (p+1)&1); cpcommit(); cpwait<1>(); }
        else cpwait<0>();
        __syncthreads();
        const float* Wb = WsF + (p&1)*4224;
        const float* Bb = BsF + (p&1)*2176;
        #pragma unroll
        for (int kk=0;kk<32;++kk){
            ulonglong2 w01 = *reinterpret_cast<const ulonglong2*>(Wb + kk*132 + rBase);
            ulonglong2 w23 = *reinterpret_cast<const ulonglong2*>(Wb + kk*132 + rBase + 4);
            float4 bv = *reinterpret_cast<const float4*>(Bb + kk*68 + cBase);
            u64 bq[4] = {dup2(bv.x), dup2(bv.y), dup2(bv.z), dup2(bv.w)};
            u64 aq[4] = {w01.x, w01.y, w23.x, w23.y};
            #pragma unroll
            for (int rr=0;rr<4;++rr)
                #pragma unroll
                for (int q=0;q<4;++q)
                    acc2[rr][q] = f2fma(aq[rr], bq[q], acc2[rr][q]);
        }
        if (p<3) __syncthreads();
    }

    const bool valid = (t0+cBase+3 < TDIM);
    float rs[8];
    #pragma unroll
    for (int k=0;k<8;++k) rs[k]=0.f;

    if (valid){
        float* po = out + ((long long)b*128 + rBase)*TDIM + t0 + cBase;
        #pragma unroll
        for (int rr=0;rr<4;++rr){
            float lo[4], hi[4];
            #pragma unroll
            for (int q=0;q<4;++q) upk2(acc2[rr][q], lo[q], hi[q]);
            int o0 = rBase + 2*rr, o1 = o0 + 1;
            float a0=sA[o0], c0=sBb[o0], bi0=sBi[o0];
            float a1=sA[o1], c1=sBb[o1], bi1=sBi[o1];
            float4 v0, v1;
            v0.x=fmaxf(lo[0]+bi0,0.f)*a0+c0; v0.y=fmaxf(lo[1]+bi0,0.f)*a0+c0;
            v0.z=fmaxf(lo[2]+bi0,0.f)*a0+c0; v0.w=fmaxf(lo[3]+bi0,0.f)*a0+c0;
            v1.x=fmaxf(hi[0]+bi1,0.f)*a1+c1; v1.y=fmaxf(hi[1]+bi1,0.f)*a1+c1;
            v1.z=fmaxf(hi[2]+bi1,0.f)*a1+c1; v1.w=fmaxf(hi[3]+bi1,0.f)*a1+c1;
            *reinterpret_cast<float4*>(po + 2*rr*TDIM)     = v0;
            *reinterpret_cast<float4*>(po + (2*rr+1)*TDIM) = v1;
            rs[2*rr]   = (v0.x+v0.y)+(v0.z+v0.w);
            rs[2*rr+1] = (v1.x+v1.y)+(v1.z+v1.w);
        }
    }
    if (spart){
        #pragma unroll
        for (int d=8; d; d>>=1)
            #pragma unroll
            for (int k=0;k<8;++k)
                rs[k] += __shfl_down_sync(0xffffffffu, rs[k], d);
        if (tx == 0){
            #pragma unroll
            for (int k=0;k<8;++k)
                spart[((long long)b*128 + rBase + k)*10 + blockIdx.x] = rs[k];
        }
    }
}

// Fused inner-conv chain: one block per (batch b, plane s)  [R12 known-good]
__global__ __launch_bounds__(256) void k_chain(
    const float* __restrict__ o1,
    const float* __restrict__ cw,
    const float* __restrict__ cb,
    const float* __restrict__ ibn,
    float* __restrict__ pl)
{
    extern __shared__ float csm[];
    float* bufA = csm;
    float* bufB = csm + 16*CCOLS;
    float* wsm  = csm + 32*CCOLS;

    const int b = blockIdx.x, s = blockIdx.y;
    const int tid = threadIdx.x;
    const int o = tid & 15, g = tid >> 4;
    const int j0 = (s == 0) ? 0 : s - 1;
    const int srcRow = (s == 0) ? 112 : (s - 1) * 16;
    const float* src = o1 + ((long long)b*128 + srcRow)*TDIM;

    for (int idx = tid; idx < 16*20*2; idx += 256) {
        int bsel = idx >= 16*20;
        int rem  = idx - bsel*16*20;
        int r = rem / 20, hc = rem - r*20;
        int c = (hc < 4) ? hc : 600 + hc;
        (bsel ? bufB : bufA)[r*CCOLS + c] = 0.f;
    }
    for (int idx = tid; idx < 16*TDIM; idx += 256) {
        int r = idx / TDIM, t = idx - r*TDIM;
        bufA[r*CCOLS + 4 + t] = src[idx];
    }

    float* cur = bufA;
    float* nxt = bufB;

    for (int j = j0; j < 7; ++j) {
        __syncthreads();
        const float* cwj = cw + j*768;
        for (int idx = tid; idx < 768; idx += 256) wsm[idx] = cwj[idx];
        __syncthreads();

        float rw[48];
        #pragma unroll
        for (int q = 0; q < 12; ++q)
            *reinterpret_cast<float4*>(&rw[q*4]) =
                *reinterpret_cast<const float4*>(&wsm[o*48 + q*4]);
        const float cb0 = __ldg(cb + j*16 + o);
        const float* ib = ibn + j*64;
        float gg=__ldg(ib+o), be=__ldg(ib+16+o), mm=__ldg(ib+32+o), vv=__ldg(ib+48+o);
        float bnA = gg*rsqrtf(vv+1e-5f), bnB = be - mm*bnA;

        #pragma unroll
        for (int p = 0; p < 5; ++p) {
            int tb = g*8 + 128*p;
            if (tb < TDIM) {
                u64 acc2[4];
                u64 cbd = dup2(cb0);
                #pragma unroll
                for (int xx=0;xx<4;++xx) acc2[xx]=cbd;
                #pragma unroll
                for (int i=0;i<16;++i){
                    const float* row = cur + i*CCOLS + tb;
                    ulonglong2 va = *reinterpret_cast<const ulonglong2*>(row);
                    ulonglong2 vb = *reinterpret_cast<const ulonglong2*>(row+4);
                    ulonglong2 vc = *reinterpret_cast<const ulonglong2*>(row+8);
                    ulonglong2 vd = *reinterpret_cast<const ulonglong2*>(row+12);
                    u64 v2[8] = {va.x,va.y,vb.x,vb.y,vc.x,vc.y,vd.x,vd.y};
                    #pragma unroll
                    for (int k=0;k<3;++k){
                        u64 w2 = dup2(rw[i*3+k]);
                        #pragma unroll
                        for (int xx=0;xx<4;++xx)
                            acc2[xx] = f2fma(w2, v2[xx+1+k], acc2[xx]);
                    }
                }
                float ov[8];
                #pragma unroll
                for (int xx=0;xx<4;++xx){
                    float lo, hi; upk2(acc2[xx], lo, hi);
                    ov[2*xx]   = fmaxf(lo,0.f)*bnA + bnB;
                    ov[2*xx+1] = fmaxf(hi,0.f)*bnA + bnB;
                }
                float* orow = nxt + o*CCOLS + 4 + tb;
                *reinterpret_cast<float4*>(orow)   = make_float4(ov[0],ov[1],ov[2],ov[3]);
                *reinterpret_cast<float4*>(orow+4) = make_float4(ov[4],ov[5],ov[6],ov[7]);
            }
        }
        __syncthreads();
        const int slot = j*(j+3)/2 + s;
        float* dst = pl + (long long)slot*PSLOT + (long long)b*PLANE;
        for (int idx = tid; idx < 16*TDIM; idx += 256) {
            int r = idx / TDIM, t = idx - r*TDIM;
            dst[idx] = nxt[r*CCOLS + 4 + t];
        }
        float* tmp = cur; cur = nxt; nxt = tmp;
    }
}

// grid (32 b, 8 j, 6 seg); threads <200 each handle 2 consecutive float4.
struct WSP { const float* w[7]; };
__global__ __launch_bounds__(256) void k_wsum(
    const float* __restrict__ pl, WSP wsp,
    const float* __restrict__ o1, float* __restrict__ o2)
{
    const int b = blockIdx.x, j = blockIdx.y, seg = blockIdx.z;
    const int tid = threadIdx.x;
    const int v0 = seg*400;
    if (tid >= 200) return;
    const int v = v0 + 2*tid;

    if (j == 7){
        const float4* s4 = reinterpret_cast<const float4*>(o1 + ((long long)b*128 + 112)*TDIM);
        float4* d4 = reinterpret_cast<float4*>(o2 + ((long long)b*128 + 112)*TDIM);
        float4 p0 = __ldg(s4 + v);
        float4 p1 = __ldg(s4 + v + 1);
        d4[v] = p0; d4[v+1] = p1;
        return;
    }
    const int off = j*(j+3)/2;
    const int S = j+2;
    float w[8];
    #pragma unroll
    for (int s=0;s<8;++s) w[s] = (s<S) ? __ldg(wsp.w[j]+s) : 0.f;
    const float4* base = reinterpret_cast<const float4*>(pl + (long long)off*PSLOT + (long long)b*PLANE);
    float4* dst = reinterpret_cast<float4*>(o2 + ((long long)b*128 + j*16)*TDIM);
    const int slotV = PSLOT/4;

    float4 a0 = make_float4(0.f,0.f,0.f,0.f);
    float4 a1 = make_float4(0.f,0.f,0.f,0.f);
    float4 b0 = make_float4(0.f,0.f,0.f,0.f);
    float4 b1 = make_float4(0.f,0.f,0.f,0.f);
    #pragma unroll
    for (int s=0;s<8;s+=2){
        if (s < S){
            float4 p = __ldg(base + (long long)s*slotV + v);
            float4 q = __ldg(base + (long long)s*slotV + v + 1);
            a0.x=fmaf(w[s],p.x,a0.x); a0.y=fmaf(w[s],p.y,a0.y);
            a0.z=fmaf(w[s],p.z,a0.z); a0.w=fmaf(w[s],p.w,a0.w);
            b0.x=fmaf(w[s],q.x,b0.x); b0.y=fmaf(w[s],q.y,b0.y);
            b0.z=fmaf(w[s],q.z,b0.z); b0.w=fmaf(w[s],q.w,b0.w);
        }
        if (s+1 < S){
            float4 p = __ldg(base + (long long)(s+1)*slotV + v);
            float4 q = __ldg(base + (long long)(s+1)*slotV + v + 1);
            a1.x=fmaf(w[s+1],p.x,a1.x); a1.y=fmaf(w[s+1],p.y,a1.y);
            a1.z=fmaf(w[s+1],p.z,a1.z); a1.w=fmaf(w[s+1],p.w,a1.w);
            b1.x=fmaf(w[s+1],q.x,b1.x); b1.y=fmaf(w[s+1],q.y,b1.y);
            b1.z=fmaf(w[s+1],q.z,b1.z); b1.w=fmaf(w[s+1],q.w,b1.w);
        }
    }
    dst[v]   = make_float4(a0.x+a1.x, a0.y+a1.y, a0.z+a1.z, a0.w+a1.w);
    dst[v+1] = make_float4(b0.x+b1.x, b0.y+b1.y, b0.z+b1.z, b0.w+b1.w);
}

// apply with SE fused: each block recomputes the SE MLP from spart (cheap,
// L1-resident), then v = o3*se_c + resid; sp = bn_o(relu(v)); nIn = sp+xNext;
// pooled[b,gcBase+c] = mean_t relu(bn_f(sp))
__global__ __launch_bounds__(128) void k_apply(
    const float* __restrict__ o3, const float* __restrict__ spart,
    const float* __restrict__ s1w, const float* __restrict__ s1b,
    const float* __restrict__ s2w, const float* __restrict__ s2b,
    const float* __restrict__ resid, long long rStr,
    const float* __restrict__ xNext, float* nIn,
    const float* __restrict__ obn, const float* __restrict__ fbn, int gcBase,
    float* __restrict__ pooled)
{
    __shared__ float m[128], s1[16], scSh;
    const int c=blockIdx.x, b=blockIdx.y, tid=threadIdx.x;
    const int gc=gcBase+c;

    {
        const float* p = spart + ((long long)b*128 + tid)*10;
        float s = 0.f;
        #pragma unroll
        for (int q=0;q<10;++q) s += p[q];
        m[tid] = s*(1.f/600.f);
    }
    __syncthreads();
    if (tid<16){
        float s=s1b[tid];
        for (int k=0;k<128;++k) s=fmaf(s1w[tid*128+k],m[k],s);
        s1[tid]=fmaxf(s,0.f);
    }
    __syncthreads();
    if (tid==0){
        float s=s2b[c];
        #pragma unroll
        for (int oo=0;oo<16;++oo) s=fmaf(s2w[c*16+oo],s1[oo],s);
        scSh = 1.f/(1.f+expf(-s));
    }
    __syncthreads();
    const float sc = scSh;

    float oA=obn[c]*rsqrtf(obn[384+c]+1e-5f);
    float oB=obn[128+c]-obn[256+c]*oA;
    float fA=fbn[gc]*rsqrtf(fbn[3072+gc]+1e-5f);
    float fB=fbn[1024+gc]-fbn[2048+gc]*fA;
    const float4* p3 = reinterpret_cast<const float4*>(o3 + ((long long)b*128+c)*TDIM);
    const float4* pr = reinterpret_cast<const float4*>(resid + (long long)b*rStr + (long long)c*TDIM);
    const float4* pn = xNext ? reinterpret_cast<const float4*>(xNext + (long long)b*1024*TDIM + (long long)c*TDIM) : nullptr;
    float4* po = reinterpret_cast<float4*>(nIn + ((long long)b*128+c)*TDIM);
    float s=0.f;
    for (int v=tid; v<150; v+=128){
        float4 a = __ldg(p3 + v);
        float4 r = __ldg(pr + v);
        float4 spv;
        spv.x = fmaxf(a.x*sc + r.x, 0.f)*oA + oB;
        spv.y = fmaxf(a.y*sc + r.y, 0.f)*oA + oB;
        spv.z = fmaxf(a.z*sc + r.z, 0.f)*oA + oB;
        spv.w = fmaxf(a.w*sc + r.w, 0.f)*oA + oB;
        if (pn){
            float4 n = __ldg(pn + v);
            po[v] = make_float4(spv.x+n.x, spv.y+n.y, spv.z+n.z, spv.w+n.w);
        }
        s += fmaxf(spv.x*fA+fB,0.f) + fmaxf(spv.y*fA+fB,0.f)
           + fmaxf(spv.z*fA+fB,0.f) + fmaxf(spv.w*fA+fB,0.f);
    }
    __shared__ float red[128];
    red[tid]=s; __syncthreads();
    for (int o=64;o;o>>=1){ if(tid<o) red[tid]+=red[tid+o]; __syncthreads(); }
    if (!tid) pooled[b*1024+gc]=red[0]*(1.f/600.f);
}

__global__ __launch_bounds__(128) void k_ptail(
    const float* __restrict__ x, const float* __restrict__ fbn,
    float* __restrict__ pooled)
{
    const int c=blockIdx.x, b=blockIdx.y, tid=threadIdx.x;
    const int gc=896+c;
    float fA=fbn[gc]*rsqrtf(fbn[3072+gc]+1e-5f);
    float fB=fbn[1024+gc]-fbn[2048+gc]*fA;
    const float4* px = reinterpret_cast<const float4*>(x + ((long long)b*1024+gc)*TDIM);
    float s=0.f;
    for (int v=tid; v<150; v+=128){
        float4 p = __ldg(px + v);
        s += fmaxf(p.x*fA+fB,0.f) + fmaxf(p.y*fA+fB,0.f)
           + fmaxf(p.z*fA+fB,0.f) + fmaxf(p.w*fA+fB,0.f);
    }
    __shared__ float red[128];
    red[tid]=s; __syncthreads();
    for (int o=64;o;o>>=1){ if(tid<o) red[tid]+=red[tid+o]; __syncthreads(); }
    if (!tid) pooled[b*1024+gc]=red[0]*(1.f/600.f);
}

__global__ __launch_bounds__(256) void k_fc(
    const float* __restrict__ pooled, const float* __restrict__ fcw,
    const float* __restrict__ fcb, float* __restrict__ out)
{
    const int b=blockIdx.x, tid=threadIdx.x;
    float s0=0.f, s1=0.f;
    for (int c=tid;c<1024;c+=256){
        float p=pooled[b*1024+c];
        s0=fmaf(p,fcw[c],s0);
        s1=fmaf(p,fcw[1024+c],s1);
    }
    __shared__ float r0[256], r1[256];
    r0[tid]=s0; r1[tid]=s1; __syncthreads();
    for (int o=128;o;o>>=1){ if(tid<o){r0[tid]+=r0[tid+o]; r1[tid]+=r1[tid+o];} __syncthreads(); }
    if (!tid){ out[b*2]=r0[0]+fcb[0]; out[b*2+1]=r1[0]+fcb[1]; }
}

extern "C" void kernel_launch(void* const* d_in, const int* in_sizes, int n_in,
                              void* d_out, int out_size)
{
    const float* P[25] = {nullptr};
    int n896=0, n3584=0, n114688=0, n14336=0;
    for (int i=0;i<n_in;++i){
        int s=in_sizes[i]; const float* p=(const float*)d_in[i];
        switch(s){
            case 19660800: P[0]=p; break;
            case 114688: P[n114688++?14:1]=p; break;
            case 896: P[n896==0?2:(n896==1?15:20)]=p; n896++; break;
            case 3584: P[n3584==0?3:(n3584==1?16:21)]=p; n3584++; break;
            case 37632: P[4]=p; break;
            case 784: P[5]=p; break;
            case 3136: P[6]=p; break;
            case 14: P[7]=p; break;  case 21: P[8]=p; break;
            case 28: P[9]=p; break;  case 35: P[10]=p; break;
            case 42: P[11]=p; break; case 49: P[12]=p; break;
            case 56: P[13]=p; break;
            case 14336: P[n14336++?19:17]=p; break;
            case 112: P[18]=p; break;
            case 4096: P[22]=p; break;
            case 2048: P[23]=p; break;
            case 2: P[24]=p; break;
            default: break;
        }
    }
    float *gin,*o1,*o2,*o3,*pl,*wt,*spart,*pool;
    cudaGetSymbolAddress((void**)&gin, g_in);
    cudaGetSymbolAddress((void**)&o1, g_o1);
    cudaGetSymbolAddress((void**)&o2, g_o2);
    cudaGetSymbolAddress((void**)&o3, g_o3);
    cudaGetSymbolAddress((void**)&pl, g_pl);
    cudaGetSymbolAddress((void**)&wt, g_wt);
    cudaGetSymbolAddress((void**)&spart, g_spart);
    cudaGetSymbolAddress((void**)&pool, g_pool);
    float* out = (float*)d_out;

    cudaFuncSetAttribute(k_chain, cudaFuncAttributeMaxDynamicSharedMemorySize, CHAIN_SMEM);
    cudaFuncSetAttribute(k_gemm,  cudaFuncAttributeMaxDynamicSharedMemorySize, GEMM_SMEM);

    k_tr<<<dim3(16,14),dim3(32,8)>>>(P[1], P[14], wt);

    dim3 gG(10,32);
    for (int i=0;i<7;++i){
        const float* xi = P[0] + (long long)i*128*TDIM;
        k_gemm<<<gG,256,GEMM_SMEM>>>(wt + i*16384, P[2]+i*128, P[3]+i*512,
                                     i? gin : xi, i? 128LL*TDIM : 1024LL*TDIM, o1, nullptr);
        k_chain<<<dim3(32,8),256,CHAIN_SMEM>>>(o1,
            P[4]+i*7*768, P[5]+i*7*16, P[6]+i*7*64, pl);
        WSP wsp;
        for (int j=0;j<7;++j) wsp.w[j] = P[7+j] + i*(j+2);
        k_wsum<<<dim3(32,8,6),256>>>(pl, wsp, o1, o2);
        k_gemm<<<gG,256,GEMM_SMEM>>>(wt + (7+i)*16384, P[15]+i*128, P[16]+i*512,
                                     o2, 128LL*TDIM, o3, spart);
        const float* xNext = (i<6) ? (P[0] + (long long)(i+1)*128*TDIM) : nullptr;
        k_apply<<<dim3(128,32),128>>>(o3, spart,
                                      P[17]+i*2048, P[18]+i*16, P[19]+i*2048, P[20]+i*128,
                                      i? gin : xi, i? 128LL*TDIM : 1024LL*TDIM,
                                      xNext, gin,
                                      P[21]+i*512, P[22], i*128, pool);
    }
    k_ptail<<<dim3(128,32),128>>>(P[0], P[22], pool);
    k_fc<<<32,256>>>(pool, P[23], P[24], out);
}

// round 15
// speedup vs baseline: 1.9121x; 1.2273x over previous
#include <cuda_runtime.h>
#include <math.h>

#define TDIM 600
#define BATCH 32
#define NBUF (BATCH*128*TDIM)
#define PLANE (16*TDIM)
#define PSLOT (BATCH*PLANE)
#define CCOLS 620
#define CHAIN_SMEM ((2*16*CCOLS + 768)*4)
#define GEMM_SMEM ((2*32*132 + 2*32*68 + 3*128)*4)

typedef unsigned long long u64;

__device__ __forceinline__ u64 dup2(float a){
    u64 r; asm("mov.b64 %0, {%1, %1};" : "=l"(r) : "f"(a)); return r;
}
__device__ __forceinline__ void upk2(u64 v, float& a, float& b){
    asm("mov.b64 {%0, %1}, %2;" : "=f"(a), "=f"(b) : "l"(v));
}
__device__ __forceinline__ u64 f2fma(u64 a, u64 b, u64 c){
    u64 d; asm("fma.rn.f32x2 %0, %1, %2, %3;" : "=l"(d) : "l"(a), "l"(b), "l"(c)); return d;
}
__device__ __forceinline__ void cpa16(unsigned dst, const void* src){
    asm volatile("cp.async.ca.shared.global [%0], [%1], 16;" :: "r"(dst), "l"(src));
}
__device__ __forceinline__ void cpa16z(unsigned dst, const void* src, int sz){
    asm volatile("cp.async.ca.shared.global [%0], [%1], 16, %2;" :: "r"(dst), "l"(src), "r"(sz));
}
__device__ __forceinline__ void cpcommit(){ asm volatile("cp.async.commit_group;"); }
template<int N> __device__ __forceinline__ void cpwait(){
    asm volatile("cp.async.wait_group %0;" :: "n"(N));
}

__device__ __align__(1024) float g_in[NBUF];
__device__ __align__(1024) float g_o1[NBUF];
__device__ __align__(1024) float g_o2[NBUF];
__device__ __align__(1024) float g_o3[NBUF];
__device__ __align__(1024) float g_pl[35*PSLOT];
__device__ __align__(1024) float g_wt[14*16384];
__device__ float g_spart[BATCH*128*10];
__device__ float g_se[BATCH*128];
__device__ float g_pool[BATCH*1024];

// transpose 14 128x128 weight matrices into g_wt[k][o]
__global__ __launch_bounds__(256) void k_tr(
    const float* __restrict__ W1, const float* __restrict__ W3,
    float* __restrict__ Wt)
{
    __shared__ float t[32][33];
    const int m = blockIdx.y;
    const int r0 = (blockIdx.x >> 2) * 32, c0 = (blockIdx.x & 3) * 32;
    const float* src = (m < 7) ? (W1 + m*16384) : (W3 + (m-7)*16384);
    float* dst = Wt + m*16384;
    const int x = threadIdx.x, y = threadIdx.y;
    #pragma unroll
    for (int k = 0; k < 4; ++k)
        t[y + 8*k][x] = src[(r0 + y + 8*k)*128 + c0 + x];
    __syncthreads();
    #pragma unroll
    for (int k = 0; k < 4; ++k)
        dst[(c0 + y + 8*k)*128 + r0 + x] = t[x][y + 8*k];
}

// out[b,o,t] = bn(relu(sum_k Wt[k,o]*in[b,k,t] + bias[o]))
// B-row source: row k >= kTail comes from tail (o1), else from in.
// optional: spart[b][o][chunk] = per-t-block partial sums for SE squeeze
__global__ __launch_bounds__(256) void k_gemm(
    const float* __restrict__ Wt, const float* __restrict__ bias,
    const float* __restrict__ bn,
    const float* __restrict__ in, long long inStr,
    const float* __restrict__ tail, int kTail,
    float* __restrict__ out, float* __restrict__ spart)
{
    extern __shared__ float sm[];
    float* WsF = sm;                 // [2][32][132]
    float* BsF = sm + 2*32*132;      // [2][32][68]
    float* sA  = sm + 2*32*132 + 2*32*68;
    float* sBb = sA + 128;
    float* sBi = sA + 256;

    const int b = blockIdx.y, t0 = blockIdx.x*64, tid = threadIdx.x;

    if (tid < 128) {
        float g=bn[tid], be=bn[128+tid], mm=bn[256+tid], vv=bn[384+tid];
        float a = g*rsqrtf(vv+1e-5f);
        sA[tid]=a; sBb[tid]=be-mm*a; sBi[tid]=bias[tid];
    }
    const float* pA = in + (long long)b*inStr;
    const float* pT = tail ? tail + (long long)b*(128LL*TDIM) : nullptr;

    unsigned smU = (unsigned)__cvta_generic_to_shared(sm);
    const unsigned wsU = smU;
    const unsigned bsU = smU + 2*32*132*4;

    u64 acc2[4][4];
    #pragma unroll
    for (int rr=0;rr<4;++rr)
        #pragma unroll
        for (int q=0;q<4;++q) acc2[rr][q]=0ull;

    const int tx = tid&15, ty = tid>>4;
    const int cBase = tx*4, rBase = ty*8;

    auto loadTile = [&](int k0, int buf){
        #pragma unroll
        for (int it=0;it<4;++it){
            int idx = it*256 + tid;
            int kk = idx >> 5, c4 = (idx & 31) << 2;
            cpa16(wsU + (unsigned)((buf*4224 + kk*132 + c4)*4),
                  Wt + (k0+kk)*128 + c4);
        }
        #pragma unroll
        for (int it=0;it<2;++it){
            int idx = it*256 + tid;
            int kk = idx >> 4, c4 = (idx & 15) << 2;
            int k = k0 + kk, t = t0 + c4;
            int sz = (t + 3 < TDIM) ? 16 : 0;
            const float* base = (k >= kTail) ? pT : pA;
            const float* src = sz ? (base + (long long)k*TDIM + t) : base;
            cpa16z(bsU + (unsigned)((buf*2176 + kk*68 + c4)*4), src, sz);
        }
    };

    loadTile(0, 0);
    cpcommit();

    #pragma unroll
    for (int p=0;p<4;++p){
        if (p<3){ loadTile((p+1)*32, (p+1)&1); cpcommit(); cpwait<1>(); }
        else cpwait<0>();
        __syncthreads();
        const float* Wb = WsF + (p&1)*4224;
        const float* Bb = BsF + (p&1)*2176;
        #pragma unroll
        for (int kk=0;kk<32;++kk){
            ulonglong2 w01 = *reinterpret_cast<const ulonglong2*>(Wb + kk*132 + rBase);
            ulonglong2 w23 = *reinterpret_cast<const ulonglong2*>(Wb + kk*132 + rBase + 4);
            float4 bv = *reinterpret_cast<const float4*>(Bb + kk*68 + cBase);
            u64 bq[4] = {dup2(bv.x), dup2(bv.y), dup2(bv.z), dup2(bv.w)};
            u64 aq[4] = {w01.x, w01.y, w23.x, w23.y};
            #pragma unroll
            for (int rr=0;rr<4;++rr)
                #pragma unroll
                for (int q=0;q<4;++q)
                    acc2[rr][q] = f2fma(aq[rr], bq[q], acc2[rr][q]);
        }
        if (p<3) __syncthreads();
    }

    const bool valid = (t0+cBase+3 < TDIM);
    float rs[8];
    #pragma unroll
    for (int k=0;k<8;++k) rs[k]=0.f;

    if (valid){
        float* po = out + ((long long)b*128 + rBase)*TDIM + t0 + cBase;
        #pragma unroll
        for (int rr=0;rr<4;++rr){
            float lo[4], hi[4];
            #pragma unroll
            for (int q=0;q<4;++q) upk2(acc2[rr][q], lo[q], hi[q]);
            int o0 = rBase + 2*rr, o1 = o0 + 1;
            float a0=sA[o0], c0=sBb[o0], bi0=sBi[o0];
            float a1=sA[o1], c1=sBb[o1], bi1=sBi[o1];
            float4 v0, v1;
            v0.x=fmaxf(lo[0]+bi0,0.f)*a0+c0; v0.y=fmaxf(lo[1]+bi0,0.f)*a0+c0;
            v0.z=fmaxf(lo[2]+bi0,0.f)*a0+c0; v0.w=fmaxf(lo[3]+bi0,0.f)*a0+c0;
            v1.x=fmaxf(hi[0]+bi1,0.f)*a1+c1; v1.y=fmaxf(hi[1]+bi1,0.f)*a1+c1;
            v1.z=fmaxf(hi[2]+bi1,0.f)*a1+c1; v1.w=fmaxf(hi[3]+bi1,0.f)*a1+c1;
            *reinterpret_cast<float4*>(po + 2*rr*TDIM)     = v0;
            *reinterpret_cast<float4*>(po + (2*rr+1)*TDIM) = v1;
            rs[2*rr]   = (v0.x+v0.y)+(v0.z+v0.w);
            rs[2*rr+1] = (v1.x+v1.y)+(v1.z+v1.w);
        }
    }
    if (spart){
        #pragma unroll
        for (int d=8; d; d>>=1)
            #pragma unroll
            for (int k=0;k<8;++k)
                rs[k] += __shfl_down_sync(0xffffffffu, rs[k], d);
        if (tx == 0){
            #pragma unroll
            for (int k=0;k<8;++k)
                spart[((long long)b*128 + rBase + k)*10 + blockIdx.x] = rs[k];
        }
    }
}

// Fused inner-conv chain: one block per (batch b, plane s)  [R12 known-good]
__global__ __launch_bounds__(256) void k_chain(
    const float* __restrict__ o1,
    const float* __restrict__ cw,
    const float* __restrict__ cb,
    const float* __restrict__ ibn,
    float* __restrict__ pl)
{
    extern __shared__ float csm[];
    float* bufA = csm;
    float* bufB = csm + 16*CCOLS;
    float* wsm  = csm + 32*CCOLS;

    const int b = blockIdx.x, s = blockIdx.y;
    const int tid = threadIdx.x;
    const int o = tid & 15, g = tid >> 4;
    const int j0 = (s == 0) ? 0 : s - 1;
    const int srcRow = (s == 0) ? 112 : (s - 1) * 16;
    const float* src = o1 + ((long long)b*128 + srcRow)*TDIM;

    for (int idx = tid; idx < 16*20*2; idx += 256) {
        int bsel = idx >= 16*20;
        int rem  = idx - bsel*16*20;
        int r = rem / 20, hc = rem - r*20;
        int c = (hc < 4) ? hc : 600 + hc;
        (bsel ? bufB : bufA)[r*CCOLS + c] = 0.f;
    }
    for (int idx = tid; idx < 16*TDIM; idx += 256) {
        int r = idx / TDIM, t = idx - r*TDIM;
        bufA[r*CCOLS + 4 + t] = src[idx];
    }

    float* cur = bufA;
    float* nxt = bufB;

    for (int j = j0; j < 7; ++j) {
        __syncthreads();
        const float* cwj = cw + j*768;
        for (int idx = tid; idx < 768; idx += 256) wsm[idx] = cwj[idx];
        __syncthreads();

        float rw[48];
        #pragma unroll
        for (int q = 0; q < 12; ++q)
            *reinterpret_cast<float4*>(&rw[q*4]) =
                *reinterpret_cast<const float4*>(&wsm[o*48 + q*4]);
        const float cb0 = __ldg(cb + j*16 + o);
        const float* ib = ibn + j*64;
        float gg=__ldg(ib+o), be=__ldg(ib+16+o), mm=__ldg(ib+32+o), vv=__ldg(ib+48+o);
        float bnA = gg*rsqrtf(vv+1e-5f), bnB = be - mm*bnA;

        #pragma unroll
        for (int p = 0; p < 5; ++p) {
            int tb = g*8 + 128*p;
            if (tb < TDIM) {
                u64 acc2[4];
                u64 cbd = dup2(cb0);
                #pragma unroll
                for (int xx=0;xx<4;++xx) acc2[xx]=cbd;
                #pragma unroll
                for (int i=0;i<16;++i){
                    const float* row = cur + i*CCOLS + tb;
                    ulonglong2 va = *reinterpret_cast<const ulonglong2*>(row);
                    ulonglong2 vb = *reinterpret_cast<const ulonglong2*>(row+4);
                    ulonglong2 vc = *reinterpret_cast<const ulonglong2*>(row+8);
                    ulonglong2 vd = *reinterpret_cast<const ulonglong2*>(row+12);
                    u64 v2[8] = {va.x,va.y,vb.x,vb.y,vc.x,vc.y,vd.x,vd.y};
                    #pragma unroll
                    for (int k=0;k<3;++k){
                        u64 w2 = dup2(rw[i*3+k]);
                        #pragma unroll
                        for (int xx=0;xx<4;++xx)
                            acc2[xx] = f2fma(w2, v2[xx+1+k], acc2[xx]);
                    }
                }
                float ov[8];
                #pragma unroll
                for (int xx=0;xx<4;++xx){
                    float lo, hi; upk2(acc2[xx], lo, hi);
                    ov[2*xx]   = fmaxf(lo,0.f)*bnA + bnB;
                    ov[2*xx+1] = fmaxf(hi,0.f)*bnA + bnB;
                }
                float* orow = nxt + o*CCOLS + 4 + tb;
                *reinterpret_cast<float4*>(orow)   = make_float4(ov[0],ov[1],ov[2],ov[3]);
                *reinterpret_cast<float4*>(orow+4) = make_float4(ov[4],ov[5],ov[6],ov[7]);
            }
        }
        __syncthreads();
        const int slot = j*(j+3)/2 + s;
        float* dst = pl + (long long)slot*PSLOT + (long long)b*PLANE;
        for (int idx = tid; idx < 16*TDIM; idx += 256) {
            int r = idx / TDIM, t = idx - r*TDIM;
            dst[idx] = nxt[r*CCOLS + 4 + t];
        }
        float* tmp = cur; cur = nxt; nxt = tmp;
    }
}

// grid (32 b, 7 j, 6 seg); threads <200 each handle 2 consecutive float4.
struct WSP { const float* w[7]; };
__global__ __launch_bounds__(256) void k_wsum(
    const float* __restrict__ pl, WSP wsp, float* __restrict__ o2)
{
    const int b = blockIdx.x, j = blockIdx.y, seg = blockIdx.z;
    const int tid = threadIdx.x;
    const int v0 = seg*400;
    if (tid >= 200) return;
    const int v = v0 + 2*tid;

    const int off = j*(j+3)/2;
    const int S = j+2;
    float w[8];
    #pragma unroll
    for (int s=0;s<8;++s) w[s] = (s<S) ? __ldg(wsp.w[j]+s) : 0.f;
    const float4* base = reinterpret_cast<const float4*>(pl + (long long)off*PSLOT + (long long)b*PLANE);
    float4* dst = reinterpret_cast<float4*>(o2 + ((long long)b*128 + j*16)*TDIM);
    const int slotV = PSLOT/4;

    float4 a0 = make_float4(0.f,0.f,0.f,0.f);
    float4 a1 = make_float4(0.f,0.f,0.f,0.f);
    float4 b0 = make_float4(0.f,0.f,0.f,0.f);
    float4 b1 = make_float4(0.f,0.f,0.f,0.f);
    #pragma unroll
    for (int s=0;s<8;s+=2){
        if (s < S){
            float4 p = __ldg(base + (long long)s*slotV + v);
            float4 q = __ldg(base + (long long)s*slotV + v + 1);
            a0.x=fmaf(w[s],p.x,a0.x); a0.y=fmaf(w[s],p.y,a0.y);
            a0.z=fmaf(w[s],p.z,a0.z); a0.w=fmaf(w[s],p.w,a0.w);
            b0.x=fmaf(w[s],q.x,b0.x); b0.y=fmaf(w[s],q.y,b0.y);
            b0.z=fmaf(w[s],q.z,b0.z); b0.w=fmaf(w[s],q.w,b0.w);
        }
        if (s+1 < S){
            float4 p = __ldg(base + (long long)(s+1)*slotV + v);
            float4 q = __ldg(base + (long long)(s+1)*slotV + v + 1);
            a1.x=fmaf(w[s+1],p.x,a1.x); a1.y=fmaf(w[s+1],p.y,a1.y);
            a1.z=fmaf(w[s+1],p.z,a1.z); a1.w=fmaf(w[s+1],p.w,a1.w);
            b1.x=fmaf(w[s+1],q.x,b1.x); b1.y=fmaf(w[s+1],q.y,b1.y);
            b1.z=fmaf(w[s+1],q.z,b1.z); b1.w=fmaf(w[s+1],q.w,b1.w);
        }
    }
    dst[v]   = make_float4(a0.x+a1.x, a0.y+a1.y, a0.z+a1.z, a0.w+a1.w);
    dst[v+1] = make_float4(b0.x+b1.x, b0.y+b1.y, b0.z+b1.z, b0.w+b1.w);
}

// SE from precomputed partial sums
__global__ __launch_bounds__(256) void k_se(
    const float* __restrict__ spart,
    const float* __restrict__ s1w, const float* __restrict__ s1b,
    const float* __restrict__ s2w, const float* __restrict__ s2b,
    float* __restrict__ seo)
{
    const int b=blockIdx.x, tid=threadIdx.x;
    __shared__ float m[128], s1[16];
    if (tid<128){
        const float* p = spart + ((long long)b*128 + tid)*10;
        float s = 0.f;
        #pragma unroll
        for (int q=0;q<10;++q) s += p[q];
        m[tid] = s*(1.f/600.f);
    }
    __syncthreads();
    if (tid<16){
        float s=s1b[tid];
        for (int c=0;c<128;++c) s=fmaf(s1w[tid*128+c],m[c],s);
        s1[tid]=fmaxf(s,0.f);
    }
    __syncthreads();
    if (tid<128){
        float s=s2b[tid];
        #pragma unroll
        for (int oo=0;oo<16;++oo) s=fmaf(s2w[tid*16+oo],s1[oo],s);
        seo[b*128+tid]=1.f/(1.f+expf(-s));
    }
}

// float4: v = o3*se + resid; sp = bn_o(relu(v)); nIn = sp + xNext;
// pooled[b,gcBase+c] = mean_t relu(bn_f(sp))
__global__ __launch_bounds__(128) void k_apply(
    const float* __restrict__ o3, const float* __restrict__ se,
    const float* __restrict__ resid, long long rStr,
    const float* __restrict__ xNext, float* nIn,
    const float* __restrict__ obn, const float* __restrict__ fbn, int gcBase,
    float* __restrict__ pooled)
{
    const int c=blockIdx.x, b=blockIdx.y, tid=threadIdx.x;
    const int gc=gcBase+c;
    float oA=obn[c]*rsqrtf(obn[384+c]+1e-5f);
    float oB=obn[128+c]-obn[256+c]*oA;
    float fA=fbn[gc]*rsqrtf(fbn[3072+gc]+1e-5f);
    float fB=fbn[1024+gc]-fbn[2048+gc]*fA;
    float sc=se[b*128+c];
    const float4* p3 = reinterpret_cast<const float4*>(o3 + ((long long)b*128+c)*TDIM);
    const float4* pr = reinterpret_cast<const float4*>(resid + (long long)b*rStr + (long long)c*TDIM);
    const float4* pn = xNext ? reinterpret_cast<const float4*>(xNext + (long long)b*1024*TDIM + (long long)c*TDIM) : nullptr;
    float4* po = reinterpret_cast<float4*>(nIn + ((long long)b*128+c)*TDIM);
    float s=0.f;
    for (int v=tid; v<150; v+=128){
        float4 a = __ldg(p3 + v);
        float4 r = __ldg(pr + v);
        float4 spv;
        spv.x = fmaxf(a.x*sc + r.x, 0.f)*oA + oB;
        spv.y = fmaxf(a.y*sc + r.y, 0.f)*oA + oB;
        spv.z = fmaxf(a.z*sc + r.z, 0.f)*oA + oB;
        spv.w = fmaxf(a.w*sc + r.w, 0.f)*oA + oB;
        if (pn){
            float4 n = __ldg(pn + v);
            po[v] = make_float4(spv.x+n.x, spv.y+n.y, spv.z+n.z, spv.w+n.w);
        }
        s += fmaxf(spv.x*fA+fB,0.f) + fmaxf(spv.y*fA+fB,0.f)
           + fmaxf(spv.z*fA+fB,0.f) + fmaxf(spv.w*fA+fB,0.f);
    }
    __shared__ float red[128];
    red[tid]=s; __syncthreads();
    for (int o=64;o;o>>=1){ if(tid<o) red[tid]+=red[tid+o]; __syncthreads(); }
    if (!tid) pooled[b*1024+gc]=red[0]*(1.f/600.f);
}

__global__ __launch_bounds__(128) void k_ptail(
    const float* __restrict__ x, const float* __restrict__ fbn,
    float* __restrict__ pooled)
{
    const int c=blockIdx.x, b=blockIdx.y, tid=threadIdx.x;
    const int gc=896+c;
    float fA=fbn[gc]*rsqrtf(fbn[3072+gc]+1e-5f);
    float fB=fbn[1024+gc]-fbn[2048+gc]*fA;
    const float4* px = reinterpret_cast<const float4*>(x + ((long long)b*1024+gc)*TDIM);
    float s=0.f;
    for (int v=tid; v<150; v+=128){
        float4 p = __ldg(px + v);
        s += fmaxf(p.x*fA+fB,0.f) + fmaxf(p.y*fA+fB,0.f)
           + fmaxf(p.z*fA+fB,0.f) + fmaxf(p.w*fA+fB,0.f);
    }
    __shared__ float red[128];
    red[tid]=s; __syncthreads();
    for (int o=64;o;o>>=1){ if(tid<o) red[tid]+=red[tid+o]; __syncthreads(); }
    if (!tid) pooled[b*1024+gc]=red[0]*(1.f/600.f);
}

__global__ __launch_bounds__(256) void k_fc(
    const float* __restrict__ pooled, const float* __restrict__ fcw,
    const float* __restrict__ fcb, float* __restrict__ out)
{
    const int b=blockIdx.x, tid=threadIdx.x;
    float s0=0.f, s1=0.f;
    for (int c=tid;c<1024;c+=256){
        float p=pooled[b*1024+c];
        s0=fmaf(p,fcw[c],s0);
        s1=fmaf(p,fcw[1024+c],s1);
    }
    __shared__ float r0[256], r1[256];
    r0[tid]=s0; r1[tid]=s1; __syncthreads();
    for (int o=128;o;o>>=1){ if(tid<o){r0[tid]+=r0[tid+o]; r1[tid]+=r1[tid+o];} __syncthreads(); }
    if (!tid){ out[b*2]=r0[0]+fcb[0]; out[b*2+1]=r1[0]+fcb[1]; }
}

extern "C" void kernel_launch(void* const* d_in, const int* in_sizes, int n_in,
                              void* d_out, int out_size)
{
    const float* P[25] = {nullptr};
    int n896=0, n3584=0, n114688=0, n14336=0;
    for (int i=0;i<n_in;++i){
        int s=in_sizes[i]; const float* p=(const float*)d_in[i];
        switch(s){
            case 19660800: P[0]=p; break;
            case 114688: P[n114688++?14:1]=p; break;
            case 896: P[n896==0?2:(n896==1?15:20)]=p; n896++; break;
            case 3584: P[n3584==0?3:(n3584==1?16:21)]=p; n3584++; break;
            case 37632: P[4]=p; break;
            case 784: P[5]=p; break;
            case 3136: P[6]=p; break;
            case 14: P[7]=p; break;  case 21: P[8]=p; break;
            case 28: P[9]=p; break;  case 35: P[10]=p; break;
            case 42: P[11]=p; break; case 49: P[12]=p; break;
            case 56: P[13]=p; break;
            case 14336: P[n14336++?19:17]=p; break;
            case 112: P[18]=p; break;
            case 4096: P[22]=p; break;
            case 2048: P[23]=p; break;
            case 2: P[24]=p; break;
            default: break;
        }
    }
    float *gin,*o1,*o2,*o3,*pl,*wt,*spart,*se,*pool;
    cudaGetSymbolAddress((void**)&gin, g_in);
    cudaGetSymbolAddress((void**)&o1, g_o1);
    cudaGetSymbolAddress((void**)&o2, g_o2);
    cudaGetSymbolAddress((void**)&o3, g_o3);
    cudaGetSymbolAddress((void**)&pl, g_pl);
    cudaGetSymbolAddress((void**)&wt, g_wt);
    cudaGetSymbolAddress((void**)&spart, g_spart);
    cudaGetSymbolAddress((void**)&se, g_se);
    cudaGetSymbolAddress((void**)&pool, g_pool);
    float* out = (float*)d_out;

    cudaFuncSetAttribute(k_chain, cudaFuncAttributeMaxDynamicSharedMemorySize, CHAIN_SMEM);
    cudaFuncSetAttribute(k_gemm,  cudaFuncAttributeMaxDynamicSharedMemorySize, GEMM_SMEM);

    k_tr<<<dim3(16,14),dim3(32,8)>>>(P[1], P[14], wt);

    dim3 gG(10,32);
    for (int i=0;i<7;++i){
        const float* xi = P[0] + (long long)i*128*TDIM;
        k_gemm<<<gG,256,GEMM_SMEM>>>(wt + i*16384, P[2]+i*128, P[3]+i*512,
                                     i? gin : xi, i? 128LL*TDIM : 1024LL*TDIM,
                                     nullptr, 128, o1, nullptr);
        k_chain<<<dim3(32,8),256,CHAIN_SMEM>>>(o1,
            P[4]+i*7*768, P[5]+i*7*16, P[6]+i*7*64, pl);
        WSP wsp;
        for (int j=0;j<7;++j) wsp.w[j] = P[7+j] + i*(j+2);
        k_wsum<<<dim3(32,7,6),256>>>(pl, wsp, o2);
        k_gemm<<<gG,256,GEMM_SMEM>>>(wt + (7+i)*16384, P[15]+i*128, P[16]+i*512,
                                     o2, 128LL*TDIM,
                                     o1, 112, o3, spart);
        k_se<<<32,256>>>(spart, P[17]+i*2048, P[18]+i*16, P[19]+i*2048, P[20]+i*128, se);
        const float* xNext = (i<6) ? (P[0] + (long long)(i+1)*128*TDIM) : nullptr;
        k_apply<<<dim3(128,32),128>>>(o3, se,
                                      i? gin : xi, i? 128LL*TDIM : 1024LL*TDIM,
                                      xNext, gin,
                                      P[21]+i*512, P[22], i*128, pool);
    }
    k_ptail<<<dim3(128,32),128>>>(P[0], P[22], pool);
    k_fc<<<32,256>>>(pool, P[23], P[24], out);
}